// round 2
// baseline (speedup 1.0000x reference)
#include <cuda_runtime.h>

// Problem constants
#define IN_DIM   225      // 15*15
#define NJ       28       // 7 scales * 4 hidden
#define NJ2      14       // NJ/2 (f32x2 pairs)
#define KC       15       // K-chunk size
#define NCHUNK   15       // 225/15
#define THREADS  128
#define ROWS_PER_BLOCK 256  // 2 rows per thread

// Precomputed parameters (written by prep kernel each launch; deterministic)
__device__ float g_W1p[IN_DIM * NJ];  // W1 folded with scale, layout [k][j=s*4+h]
__device__ float g_V[NJ];             // 2^s * sum_k W2[s,h,k] / 28
__device__ float g_C;                 // sum_{s,k} 2^s * b2[s,k] / 28

typedef unsigned long long ull;

__device__ __forceinline__ ull pack2(float lo, float hi) {
    ull r; asm("mov.b64 %0,{%1,%2};" : "=l"(r) : "f"(lo), "f"(hi)); return r;
}
__device__ __forceinline__ void unpack2(ull v, float& lo, float& hi) {
    asm("mov.b64 {%0,%1},%2;" : "=f"(lo), "=f"(hi) : "l"(v));
}
__device__ __forceinline__ void fma2(ull& d, ull a, ull b) {
    asm("fma.rn.f32x2 %0,%1,%2,%0;" : "+l"(d) : "l"(a), "l"(b));
}

__device__ __forceinline__ float gelu_exact(float v) {
    return 0.5f * v * (1.0f + erff(v * 0.70710678118654752440f));
}
__device__ __forceinline__ float softplus_stable(float r) {
    return fmaxf(r, 0.0f) + log1pf(expf(-fabsf(r)));
}

// ---------------------------------------------------------------------------
// Prep: fold scales into W1, collapse layer-2 + /scale + mean into (V, C).
// Tiny (6300 elems), one block.
// ---------------------------------------------------------------------------
__global__ void prep_kernel(const float* __restrict__ W1,
                            const float* __restrict__ W2,
                            const float* __restrict__ b2) {
    int t = threadIdx.x;
    for (int i = t; i < IN_DIM * NJ; i += 256) {
        int k = i / NJ;
        int j = i - k * NJ;
        int s = j >> 2;
        int h = j & 3;
        // W1 layout: [s][k][h] = s*900 + k*4 + h ; scale = 2^-s
        g_W1p[i] = W1[s * (IN_DIM * 4) + k * 4 + h] * exp2f(-(float)s);
    }
    if (t < NJ) {
        int s = t >> 2, h = t & 3;
        float sum = 0.0f;
        #pragma unroll
        for (int k4 = 0; k4 < 4; ++k4) sum += W2[s * 16 + h * 4 + k4];
        g_V[t] = sum * exp2f((float)s) * (1.0f / 28.0f);
    }
    if (t == 0) {
        float c = 0.0f;
        for (int s = 0; s < 7; ++s) {
            float inv = exp2f((float)s);
            #pragma unroll
            for (int k4 = 0; k4 < 4; ++k4) c += b2[s * 4 + k4] * inv;
        }
        g_C = c * (1.0f / 28.0f);
    }
}

// ---------------------------------------------------------------------------
// Main: per-row 225x28 GEMM (f32x2 packed FMA) + GELU + fused reduction.
// 128 threads, 2 rows/thread, x staged in shared in 15-wide K-chunks.
// ---------------------------------------------------------------------------
__global__ __launch_bounds__(THREADS, 4)
void mlp_main_kernel(const float* __restrict__ x,
                     const float* __restrict__ b1,
                     float* __restrict__ out) {
    __shared__ __align__(16) float sw[IN_DIM * NJ];       // 25200 B
    __shared__ float sx[ROWS_PER_BLOCK * KC];             // 15360 B
    __shared__ float sV[NJ];
    __shared__ float sC;

    int tid = threadIdx.x;

    // Stage folded weights + reduction vector into shared
    for (int i = tid; i < IN_DIM * NJ; i += THREADS) sw[i] = g_W1p[i];
    if (tid < NJ)  sV[tid] = g_V[tid];
    if (tid == 0)  sC = g_C;

    // Accumulators init = b1 (bias fold). Row A = base+tid, Row B = base+tid+128.
    ull accA[NJ2], accB[NJ2];
    #pragma unroll
    for (int j2 = 0; j2 < NJ2; ++j2) {
        float lo = b1[2 * j2], hi = b1[2 * j2 + 1];
        accA[j2] = pack2(lo, hi);
        accB[j2] = accA[j2];
    }

    int base = (int)blockIdx.x * ROWS_PER_BLOCK;
    const float* gx = x + (long long)base * IN_DIM;

    for (int c = 0; c < NCHUNK; ++c) {
        // Stage x chunk [256 rows][15 cols] (coalesced-ish: contiguous runs of 15)
        for (int i = tid; i < ROWS_PER_BLOCK * KC; i += THREADS) {
            int r = i / KC;
            int col = i - r * KC;
            sx[i] = gx[r * IN_DIM + c * KC + col];
        }
        __syncthreads();

        #pragma unroll
        for (int k = 0; k < KC; ++k) {
            float xA = sx[tid * KC + k];                      // stride 15: conflict-free
            float xB = sx[(tid + THREADS) * KC + k];
            ull pA = pack2(xA, xA);
            ull pB = pack2(xB, xB);
            const ull* w = (const ull*)(sw + (c * KC + k) * NJ);  // 8B-aligned (even idx)
            #pragma unroll
            for (int j2 = 0; j2 < NJ2; ++j2) {
                ull wv = w[j2];                               // LDS.64 broadcast
                fma2(accA[j2], pA, wv);
                fma2(accB[j2], pB, wv);
            }
        }
        __syncthreads();
    }

    // Epilogue: exact GELU + fused (layer2 + /scale + mean) dot + softplus
    float rA = sC, rB = sC;
    #pragma unroll
    for (int j2 = 0; j2 < NJ2; ++j2) {
        float h0, h1;
        unpack2(accA[j2], h0, h1);
        rA += gelu_exact(h0) * sV[2 * j2] + gelu_exact(h1) * sV[2 * j2 + 1];
        unpack2(accB[j2], h0, h1);
        rB += gelu_exact(h0) * sV[2 * j2] + gelu_exact(h1) * sV[2 * j2 + 1];
    }
    out[base + tid]           = softplus_stable(rA);
    out[base + tid + THREADS] = softplus_stable(rB);
}

// ---------------------------------------------------------------------------
extern "C" void kernel_launch(void* const* d_in, const int* in_sizes, int n_in,
                              void* d_out, int out_size) {
    const float* x  = (const float*)d_in[0];
    const float* W1 = (const float*)d_in[1];
    const float* b1 = (const float*)d_in[2];
    const float* W2 = (const float*)d_in[3];
    const float* b2 = (const float*)d_in[4];
    float* out = (float*)d_out;

    prep_kernel<<<1, 256>>>(W1, W2, b2);

    int blocks = out_size / ROWS_PER_BLOCK;   // 262144/256 = 1024
    mlp_main_kernel<<<blocks, THREADS>>>(x, b1, out);
}